// round 4
// baseline (speedup 1.0000x reference)
#include <cuda_runtime.h>
#include <mma.h>
#include <stdint.h>

using namespace nvcuda;

#define NSTAGE 3
#define CH_ELEMS (64 * 68)
#define CH_BYTES (CH_ELEMS * 4)  // 17408

// dynamic smem layout (bytes)
#define OFF_MBAR 0u                              // full[3]@0,16,32 ; empty[3]@48,64,80
#define OFF_T 128u                               // t_range, 25 f32
#define OFF_B2 256u                              // 256 f32
#define OFF_B1WT 1280u                           // 256 float2
#define OFF_ZBUF 3584u                           // 128 x 260 f32 (tf32 images)
#define OFF_HBUF (OFF_ZBUF + 128u * 260u * 4u)   // 136704: 128 x 68 f32
#define OFF_RING (OFF_HBUF + 128u * 68u * 4u)    // 171520 (128-aligned)
#define DYN_SMEM (OFF_RING + NSTAGE * CH_BYTES)  // 223744

// prep output: [2 mats][4 kb][4 nb] chunks of [64][68] tf32-rounded floats
__device__ __align__(128) float g_wblk[2 * 16 * CH_ELEMS];

// ---------- helpers ----------
__device__ __forceinline__ uint32_t smem_u32(const void* p) {
    uint32_t a;
    asm("{ .reg .u64 t; cvta.to.shared.u64 t, %1; cvt.u32.u64 %0, t; }" : "=r"(a) : "l"(p));
    return a;
}
__device__ __forceinline__ float tf32r(float x) {
    float y; asm("cvt.rna.tf32.f32 %0, %1;" : "=f"(y) : "f"(x));
    return y;
}
__device__ __forceinline__ float tanh_acc(float x) {
    // tanh(x) = 1 - 2/(1 + e^{2x}); ex2/rcp approx ~2^-22 rel err; correct saturation.
    float u = x * 2.885390081777927f;  // 2*log2(e)
    float e; asm("ex2.approx.f32 %0, %1;" : "=f"(e) : "f"(u));
    float r; asm("rcp.approx.f32 %0, %1;" : "=f"(r) : "f"(e + 1.0f));
    return fmaf(-2.0f, r, 1.0f);
}

#define MBINIT(addr, cnt) \
    asm volatile("mbarrier.init.shared.b64 [%0], %1;" :: "r"(addr), "r"(cnt) : "memory")
#define MB_TX(addr, bytes) \
    asm volatile("mbarrier.arrive.expect_tx.shared.b64 _, [%0], %1;" :: "r"(addr), "r"(bytes) : "memory")
#define MB_ARRIVE(addr) \
    asm volatile("mbarrier.arrive.shared.b64 _, [%0];" :: "r"(addr) : "memory")

#define WAITP(addr, par) do { \
    uint32_t _m = (addr), _p = (par), _d; \
    asm volatile("{\n\t.reg .pred p;\n\t" \
        "mbarrier.try_wait.parity.acquire.cta.shared::cta.b64 p, [%1], %2;\n\t" \
        "selp.b32 %0, 1, 0, p;\n\t}" : "=r"(_d) : "r"(_m), "r"(_p) : "memory"); \
    if (!_d) { \
        asm volatile("{\n\t.reg .pred P1;\n\t" \
            "WL_%=:\n\t" \
            "mbarrier.try_wait.parity.acquire.cta.shared::cta.b64 P1, [%0], %1, 0x989680;\n\t" \
            "@P1 bra.uni WD_%=;\n\tbra.uni WL_%=;\n\tWD_%=:\n\t}" \
            :: "r"(_m), "r"(_p) : "memory"); \
    } \
} while (0)

#define WAITPR(addr, par) do { \
    uint32_t _m = (addr), _p = (par), _d; \
    asm volatile("{\n\t.reg .pred p;\n\t" \
        "mbarrier.try_wait.parity.relaxed.cta.shared::cta.b64 p, [%1], %2, 0x989680;\n\t" \
        "selp.b32 %0, 1, 0, p;\n\t}" : "=r"(_d) : "r"(_m), "r"(_p) : "memory"); \
    if (!_d) { \
        asm volatile("{\n\t.reg .pred P1;\n\t" \
            "WL_%=:\n\t" \
            "mbarrier.try_wait.parity.relaxed.cta.shared::cta.b64 P1, [%0], %1, 0x989680;\n\t" \
            "@P1 bra.uni WD_%=;\n\tbra.uni WL_%=;\n\tWD_%=:\n\t}" \
            :: "r"(_m), "r"(_p) : "memory"); \
    } \
} while (0)

#define BAR1() asm volatile("bar.sync 1, 256;" ::: "memory")

__device__ __forceinline__ void bulk_g2s(uint32_t dst, const void* src, uint32_t bytes, uint32_t mbar) {
    asm volatile(
        "cp.async.bulk.shared::cluster.global.mbarrier::complete_tx::bytes [%0], [%1], %2, [%3];"
        :: "r"(dst), "l"(src), "r"(bytes), "r"(mbar) : "memory");
}

// ---------- prep: tf32-round + chunk re-tile of both weight matrices ----------
// chunk b = mat*16 + kb*4 + nb holds W[kb*64..+64 rows][nb*64..+64 cols] as [64][68] (padded ld).
extern "C" __global__ void __launch_bounds__(256) ode_prep(
    const float* __restrict__ W1, const float* __restrict__ W2) {
    int b = blockIdx.x;  // 0..31
    int mat = b >> 4, kb = (b >> 2) & 3, nb = b & 3;
    const float* W = mat ? W2 : W1;
    for (int e = threadIdx.x; e < 4096; e += 256) {
        int r = e >> 6, c = e & 63;
        g_wblk[b * CH_ELEMS + r * 68 + c] = tf32r(W[(kb * 64 + r) * 256 + nb * 64 + c]);
    }
}

// ---------- main persistent kernel ----------
// 128 CTAs x 128 rows. Warps 0-7 compute (16 rows each), warp 8 lane 0 = weight producer.
extern "C" __global__ void __launch_bounds__(288, 1) ode_main(
    const float* __restrict__ z0, const float* __restrict__ t_range,
    const float* __restrict__ b1, const float* __restrict__ wt,
    const float* __restrict__ b2, float* __restrict__ out) {
    extern __shared__ char smem[];
    const uint32_t sb = smem_u32(smem);
    const int tid = threadIdx.x, w = tid >> 5, lane = tid & 31;
    const int row0 = blockIdx.x * 128;

    float* ZB = (float*)(smem + OFF_ZBUF);
    float* HB = (float*)(smem + OFF_HBUF);
    float* RING = (float*)(smem + OFF_RING);
    float* sT = (float*)(smem + OFF_T);
    float* sB2 = (float*)(smem + OFF_B2);
    float2* sBW = (float2*)(smem + OFF_B1WT);

    if (tid == 0) {
        for (int s = 0; s < NSTAGE; s++) { MBINIT(sb + 16u * s, 1); MBINIT(sb + 48u + 16u * s, 256); }
    }
    if (tid < 256) {
        sB2[tid] = b2[tid];
        sBW[tid] = make_float2(b1[tid], wt[tid]);
        if (tid < 25) sT[tid] = t_range[tid];
        // init z master (in out) and its tf32 image (in ZB); thread owns column tid.
        for (int r = 0; r < 128; r++) {
            float v = z0[(size_t)(row0 + r) * 256 + tid];
            out[(size_t)(row0 + r) * 256 + tid] = v;
            ZB[r * 260 + tid] = tf32r(v);
        }
    }
    __syncthreads();

    if (w == 8) {
        // ---- producer: stream 25 steps x 32 chunks through the 3-stage ring ----
        if (lane == 0) {
            uint32_t es = 0, ep = 1;
            for (int i = 0; i < 25 * 32; i++) {
                int j = i & 31, q = j >> 3, lo = j & 7;
                int chunk = (lo < 4) ? (lo * 4 + q) : (16 + q * 4 + (lo - 4));
                WAITPR(sb + 48u + 16u * es, ep);
                MB_TX(sb + 16u * es, CH_BYTES);
                bulk_g2s(sb + OFF_RING + es * CH_BYTES, g_wblk + chunk * CH_ELEMS, CH_BYTES,
                         sb + 16u * es);
                es++; if (es == NSTAGE) { es = 0; ep ^= 1; }
            }
        }
        return;
    }

    // ---- compute warps (tid < 256) ----
    const float dt = sT[1] - sT[0];
    const int rw = w * 16;  // this warp's first row
    uint32_t cs = 0, cp = 0;

    wmma::fragment<wmma::accumulator, 16, 16, 8, float> D2[16];
    wmma::fragment<wmma::accumulator, 16, 16, 8, float> D1[4];
    wmma::fragment<wmma::matrix_a, 16, 16, 8, wmma::precision::tf32, wmma::row_major> af;
    wmma::fragment<wmma::matrix_b, 16, 16, 8, wmma::precision::tf32, wmma::row_major> bf;

    for (int s = 0; s < 25; s++) {
        const float t = sT[s];
#pragma unroll
        for (int n = 0; n < 16; n++) wmma::fill_fragment(D2[n], 0.0f);

        for (int q = 0; q < 4; q++) {
            // ---- GEMM1 quarter: D1[128, 64q..64q+64] = z @ W1[:, quarter] ----
#pragma unroll
            for (int n = 0; n < 4; n++) wmma::fill_fragment(D1[n], 0.0f);
            for (int kb = 0; kb < 4; kb++) {
                WAITP(sb + 16u * cs, cp);
                const float* ck = RING + cs * CH_ELEMS;
#pragma unroll
                for (int k8 = 0; k8 < 8; k8++) {
                    wmma::load_matrix_sync(af, ZB + rw * 260 + (kb * 64 + k8 * 8), 260);
#pragma unroll
                    for (int nt = 0; nt < 4; nt++) {
                        wmma::load_matrix_sync(bf, ck + (k8 * 8) * 68 + nt * 16, 68);
                        wmma::mma_sync(D1[nt], af, bf, D1[nt]);
                    }
                }
                MB_ARRIVE(sb + 48u + 16u * cs);
                cs++; if (cs == NSTAGE) { cs = 0; cp ^= 1; }
            }
            BAR1();  // HBUF free (everyone done with previous quarter's h)
#pragma unroll
            for (int nt = 0; nt < 4; nt++)
                wmma::store_matrix_sync(HB + rw * 68 + nt * 16, D1[nt], 68, wmma::mem_row_major);
            BAR1();
            // pointwise: h = tanh(x + b1 + t*wt), tf32-rounded in place
#pragma unroll 4
            for (int i = 0; i < 32; i++) {
                int idx = tid + (i << 8);
                int r = idx >> 6, c = idx & 63;
                float2 bw = sBW[q * 64 + c];
                float x = HB[r * 68 + c] + bw.x + t * bw.y;
                HB[r * 68 + c] = tf32r(tanh_acc(x));
            }
            BAR1();
            // ---- GEMM2 partial: D2 += h_quarter @ W2[64q..64q+64, :] ----
            for (int nb = 0; nb < 4; nb++) {
                WAITP(sb + 16u * cs, cp);
                const float* ck = RING + cs * CH_ELEMS;
#pragma unroll
                for (int k8 = 0; k8 < 8; k8++) {
                    wmma::load_matrix_sync(af, HB + rw * 68 + k8 * 8, 68);
#pragma unroll
                    for (int nt = 0; nt < 4; nt++) {
                        wmma::load_matrix_sync(bf, ck + (k8 * 8) * 68 + nt * 16, 68);
                        wmma::mma_sync(D2[nb * 4 + nt], af, bf, D2[nb * 4 + nt]);
                    }
                }
                MB_ARRIVE(sb + 48u + 16u * cs);
                cs++; if (cs == NSTAGE) { cs = 0; cp ^= 1; }
            }
        }
        BAR1();  // all warps done reading ZB (GEMM1 of q=3) -> ZB reusable
#pragma unroll
        for (int n = 0; n < 16; n++)
            wmma::store_matrix_sync(ZB + rw * 260 + n * 16, D2[n], 260, wmma::mem_row_major);
        BAR1();
        // epilogue: z_new = z + dt*(D2 + b2); master fp32 in out, tf32 image in ZB
        {
            const float bc = sB2[tid];
#pragma unroll 4
            for (int r = 0; r < 128; r++) {
                float d2v = ZB[r * 260 + tid];
                size_t g = (size_t)(row0 + r) * 256 + tid;
                float zn = out[g] + dt * (d2v + bc);
                out[g] = zn;
                ZB[r * 260 + tid] = tf32r(zn);
            }
        }
        BAR1();
    }
}

extern "C" void kernel_launch(void* const* d_in, const int* in_sizes, int n_in,
                              void* d_out, int out_size) {
    const float* z0 = (const float*)d_in[0];
    const float* t_range = (const float*)d_in[1];
    const float* W1 = (const float*)d_in[2];
    const float* b1 = (const float*)d_in[3];
    const float* wt = (const float*)d_in[4];
    const float* W2 = (const float*)d_in[5];
    const float* b2 = (const float*)d_in[6];
    float* out = (float*)d_out;

    cudaFuncSetAttribute(ode_main, cudaFuncAttributeMaxDynamicSharedMemorySize, DYN_SMEM);
    ode_prep<<<32, 256>>>(W1, W2);
    ode_main<<<128, 288, DYN_SMEM>>>(z0, t_range, b1, wt, b2, out);
}

// round 5
// speedup vs baseline: 3.0221x; 3.0221x over previous
#include <cuda_runtime.h>
#include <stdint.h>

#define NSTAGE 2
#define CH_ELEMS 8192u   // one 32KB chunk: [4 kt][32 nt][32 lane][2] tf32
#define CH_BYTES 32768u

// dynamic smem layout (bytes)
#define OFF_T 128u                               // t_range 25 f32
#define OFF_BW 256u                              // float2 (b1, wt)[256] -> 2048B
#define OFF_B2 2304u                             // f32 b2[256] -> 1024B
#define OFF_ZH 3584u                             // 128x256 tf32 in A-frag order = 131072B
#define OFF_RING (OFF_ZH + 131072u)              // 134656
#define DYN_SMEM (OFF_RING + NSTAGE * CH_BYTES)  // 200192

// prep output: 16 chunks (W1 slabs 0-7, W2 slabs 8-15) of 32KB in B-frag order
__device__ __align__(128) float g_wblk[16 * CH_ELEMS];

// ---------- helpers ----------
__device__ __forceinline__ uint32_t smem_u32(const void* p) {
    uint32_t a;
    asm("{ .reg .u64 t; cvta.to.shared.u64 t, %1; cvt.u32.u64 %0, t; }" : "=r"(a) : "l"(p));
    return a;
}
__device__ __forceinline__ float tf32r(float x) {
    float y; asm("cvt.rna.tf32.f32 %0, %1;" : "=f"(y) : "f"(x));
    return y;
}
__device__ __forceinline__ float tanh_acc(float x) {
    // tanh(x) = 1 - 2/(1 + e^{2x}); ex2/rcp approx ~2^-22 rel err; correct saturation.
    float u = x * 2.885390081777927f;  // 2*log2(e)
    float e; asm("ex2.approx.f32 %0, %1;" : "=f"(e) : "f"(u));
    float r; asm("rcp.approx.f32 %0, %1;" : "=f"(r) : "f"(e + 1.0f));
    return fmaf(-2.0f, r, 1.0f);
}

#define MBINIT(addr, cnt) \
    asm volatile("mbarrier.init.shared.b64 [%0], %1;" :: "r"(addr), "r"(cnt) : "memory")
#define MB_TX(addr, bytes) \
    asm volatile("mbarrier.arrive.expect_tx.shared.b64 _, [%0], %1;" :: "r"(addr), "r"(bytes) : "memory")
#define MB_ARRIVE(addr) \
    asm volatile("mbarrier.arrive.shared.b64 _, [%0];" :: "r"(addr) : "memory")

#define WAITP(addr, par) do { \
    uint32_t _m = (addr), _p = (par), _d; \
    asm volatile("{\n\t.reg .pred p;\n\t" \
        "mbarrier.try_wait.parity.acquire.cta.shared::cta.b64 p, [%1], %2;\n\t" \
        "selp.b32 %0, 1, 0, p;\n\t}" : "=r"(_d) : "r"(_m), "r"(_p) : "memory"); \
    if (!_d) { \
        asm volatile("{\n\t.reg .pred P1;\n\t" \
            "WL_%=:\n\t" \
            "mbarrier.try_wait.parity.acquire.cta.shared::cta.b64 P1, [%0], %1, 0x989680;\n\t" \
            "@P1 bra.uni WD_%=;\n\tbra.uni WL_%=;\n\tWD_%=:\n\t}" \
            :: "r"(_m), "r"(_p) : "memory"); \
    } \
} while (0)

#define WAITPR(addr, par) do { \
    uint32_t _m = (addr), _p = (par), _d; \
    asm volatile("{\n\t.reg .pred p;\n\t" \
        "mbarrier.try_wait.parity.relaxed.cta.shared::cta.b64 p, [%1], %2, 0x989680;\n\t" \
        "selp.b32 %0, 1, 0, p;\n\t}" : "=r"(_d) : "r"(_m), "r"(_p) : "memory"); \
    if (!_d) { \
        asm volatile("{\n\t.reg .pred P1;\n\t" \
            "WL_%=:\n\t" \
            "mbarrier.try_wait.parity.relaxed.cta.shared::cta.b64 P1, [%0], %1, 0x989680;\n\t" \
            "@P1 bra.uni WD_%=;\n\tbra.uni WL_%=;\n\tWD_%=:\n\t}" \
            :: "r"(_m), "r"(_p) : "memory"); \
    } \
} while (0)

#define BAR1() asm volatile("bar.sync 1, 256;" ::: "memory")

__device__ __forceinline__ void bulk_g2s(uint32_t dst, const void* src, uint32_t bytes, uint32_t mbar) {
    asm volatile(
        "cp.async.bulk.shared::cluster.global.mbarrier::complete_tx::bytes [%0], [%1], %2, [%3];"
        :: "r"(dst), "l"(src), "r"(bytes), "r"(mbar) : "memory");
}

// mma.sync m16n8k8 tf32: d,a,b,c layouts per PTX ISA (g=lane>>2, t=lane&3):
// a0=(g,t) a1=(g+8,t) a2=(g,t+4) a3=(g+8,t+4); b0=(t,g) b1=(t+4,g);
// c0=(g,2t) c1=(g,2t+1) c2=(g+8,2t) c3=(g+8,2t+1)
#define MMA8(d, a, b) \
    asm volatile("mma.sync.aligned.m16n8k8.row.col.f32.tf32.tf32.f32 " \
        "{%0,%1,%2,%3}, {%4,%5,%6,%7}, {%8,%9}, {%0,%1,%2,%3};" \
        : "+f"((d)[0]), "+f"((d)[1]), "+f"((d)[2]), "+f"((d)[3]) \
        : "r"((a).x), "r"((a).y), "r"((a).z), "r"((a).w), "r"((b).x), "r"((b).y))

// A-fragment-order store into ZH: logical (row 0..127, col 0..255)
__device__ __forceinline__ void zh_store(float* ZH, int row, int col, float v) {
    int tile = ((row >> 4) << 5) + (col >> 3);
    int dl = ((row & 7) << 2) + (col & 3);
    int rr = ((row >> 3) & 1) + (((col >> 2) & 1) << 1);
    ZH[tile * 128 + dl * 4 + rr] = v;
}

// ---------- prep: tf32-round + B-fragment-order k-slab images ----------
// chunk b = mat*8 + slab: B[k][n] = W[k][n], k in [slab*32, +32), n in [0,256)
// layout: idx = ((kt*32 + nt)*32 + lane)*2 + r ; k = slab*32+kt*8+(lane&3)+4r ; n = nt*8+(lane>>2)
extern "C" __global__ void __launch_bounds__(256) ode_prep(
    const float* __restrict__ W1, const float* __restrict__ W2) {
    int b = blockIdx.x, mat = b >> 3, slab = b & 7;
    const float* W = mat ? W2 : W1;
    for (int e = threadIdx.x; e < (int)CH_ELEMS; e += 256) {
        int r = e & 1, lane = (e >> 1) & 31, nt = (e >> 6) & 31, kt = e >> 11;
        int k = slab * 32 + kt * 8 + (lane & 3) + 4 * r;
        int n = nt * 8 + (lane >> 2);
        g_wblk[b * CH_ELEMS + e] = tf32r(W[k * 256 + n]);
    }
}

// ---------- GEMM pass: D[64x64 per warp] += A(ZH) @ B(ring), k=256 ----------
__device__ __forceinline__ void gemm_pass(
    float (&d)[4][8][4], const char* smem, uint32_t sb,
    int mi, int ni, int lane, uint32_t& cs, uint32_t& cp) {
    const uint4* A = (const uint4*)(smem + OFF_ZH);
    for (int kc = 0; kc < 8; kc++) {
        WAITP(sb + 16u * cs, cp);
        const uint2* Bk = (const uint2*)(smem + OFF_RING + cs * CH_BYTES);
#pragma unroll
        for (int kk = 0; kk < 4; kk++) {
            const int ktg = kc * 4 + kk;
            uint4 a[4];
#pragma unroll
            for (int i = 0; i < 4; i++) a[i] = A[((mi * 4 + i) * 32 + ktg) * 32 + lane];
            uint2 b[8];
#pragma unroll
            for (int j = 0; j < 8; j++) b[j] = Bk[(kk * 32 + ni * 8 + j) * 32 + lane];
#pragma unroll
            for (int i = 0; i < 4; i++)
#pragma unroll
                for (int j = 0; j < 8; j++) MMA8(d[i][j], a[i], b[j]);
        }
        if (lane == 0) MB_ARRIVE(sb + 48u + 16u * cs);
        cs++; if (cs == NSTAGE) { cs = 0; cp ^= 1; }
    }
}

// ---------- main persistent kernel ----------
// 128 CTAs x 128 rows; warps 0-7 compute (2x4 grid of 64x64 tiles), warp 8 = producer.
extern "C" __global__ void __launch_bounds__(288, 1) ode_main(
    const float* __restrict__ z0, const float* __restrict__ t_range,
    const float* __restrict__ b1, const float* __restrict__ wt,
    const float* __restrict__ b2, float* __restrict__ out) {
    extern __shared__ char smem[];
    const uint32_t sb = smem_u32(smem);
    const int tid = threadIdx.x, w = tid >> 5, lane = tid & 31;
    const int row0 = blockIdx.x * 128;

    float* ZH = (float*)(smem + OFF_ZH);
    float* sT = (float*)(smem + OFF_T);
    float2* sBW = (float2*)(smem + OFF_BW);
    float* sB2 = (float*)(smem + OFF_B2);

    if (tid == 0) {
        for (int s = 0; s < NSTAGE; s++) {
            MBINIT(sb + 16u * s, 1);        // full: producer MB_TX(1 arrive) + bulk bytes
            MBINIT(sb + 48u + 16u * s, 8);  // empty: one arrive per compute warp
        }
    }
    if (tid < 256) {
        sB2[tid] = b2[tid];
        sBW[tid] = make_float2(b1[tid], wt[tid]);
        if (tid < 25) sT[tid] = t_range[tid];
        // init: z master -> out, tf32 image -> ZH (thread owns half a row)
        const int row = tid >> 1, cb = (tid & 1) * 128;
        const float4* zp = (const float4*)(z0 + (size_t)(row0 + row) * 256 + cb);
        float4* op = (float4*)(out + (size_t)(row0 + row) * 256 + cb);
#pragma unroll 4
        for (int q = 0; q < 32; q++) {
            float4 v = zp[q];
            op[q] = v;
            int c = cb + q * 4;
            zh_store(ZH, row, c + 0, tf32r(v.x));
            zh_store(ZH, row, c + 1, tf32r(v.y));
            zh_store(ZH, row, c + 2, tf32r(v.z));
            zh_store(ZH, row, c + 3, tf32r(v.w));
        }
    }
    __syncthreads();

    if (w == 8) {
        // ---- producer: 25 steps x 16 chunks (W1 slabs 0-7 then W2 slabs 8-15) ----
        if (lane == 0) {
            uint32_t es = 0, ep = 1;
            for (int i = 0; i < 400; i++) {
                WAITPR(sb + 48u + 16u * es, ep);
                MB_TX(sb + 16u * es, CH_BYTES);
                bulk_g2s(sb + OFF_RING + es * CH_BYTES, g_wblk + (i & 15) * CH_ELEMS,
                         CH_BYTES, sb + 16u * es);
                es++; if (es == NSTAGE) { es = 0; ep ^= 1; }
            }
        }
        return;
    }

    // ---- compute warps ----
    const int mi = w >> 2, ni = w & 3;  // warp tile: rows [mi*64,+64), cols [ni*64,+64)
    const int gid = lane >> 2, tig = lane & 3;
    const float dt = sT[1] - sT[0];
    uint32_t cs = 0, cp = 0;
    float d[4][8][4];

    for (int s = 0; s < 25; s++) {
        const float t = sT[s];
        // ---- GEMM1: D = z @ W1 ----
#pragma unroll
        for (int i = 0; i < 4; i++)
#pragma unroll
            for (int j = 0; j < 8; j++)
#pragma unroll
                for (int r = 0; r < 4; r++) d[i][j][r] = 0.0f;
        gemm_pass(d, smem, sb, mi, ni, lane, cs, cp);
        BAR1();  // all warps done reading ZH (z)
        // ---- h = tanh(D + b1 + t*wt) -> ZH (tf32, A-frag order; col is GEMM2's k) ----
#pragma unroll
        for (int i = 0; i < 4; i++)
#pragma unroll
            for (int j = 0; j < 8; j++)
#pragma unroll
                for (int r = 0; r < 4; r++) {
                    int row = mi * 64 + i * 16 + gid + ((r & 2) ? 8 : 0);
                    int col = ni * 64 + j * 8 + 2 * tig + (r & 1);
                    float2 bw = sBW[col];
                    float x = d[i][j][r] + bw.x + t * bw.y;
                    zh_store(ZH, row, col, tf32r(tanh_acc(x)));
                }
        BAR1();  // h fully written
        // ---- GEMM2: D = h @ W2 ----
#pragma unroll
        for (int i = 0; i < 4; i++)
#pragma unroll
            for (int j = 0; j < 8; j++)
#pragma unroll
                for (int r = 0; r < 4; r++) d[i][j][r] = 0.0f;
        gemm_pass(d, smem, sb, mi, ni, lane, cs, cp);
        BAR1();  // all warps done reading ZH (h)
        // ---- z update: z += dt*(D + b2); fp32 master in out, tf32 image -> ZH ----
#pragma unroll
        for (int i = 0; i < 4; i++)
#pragma unroll
            for (int j = 0; j < 8; j++)
#pragma unroll
                for (int rp = 0; rp < 2; rp++) {
                    int row = mi * 64 + i * 16 + gid + rp * 8;
                    int col = ni * 64 + j * 8 + 2 * tig;
                    size_t g = (size_t)(row0 + row) * 256 + col;
                    float2 zo = *(const float2*)(out + g);
                    float zn0 = fmaf(dt, d[i][j][2 * rp + 0] + sB2[col + 0], zo.x);
                    float zn1 = fmaf(dt, d[i][j][2 * rp + 1] + sB2[col + 1], zo.y);
                    *(float2*)(out + g) = make_float2(zn0, zn1);
                    zh_store(ZH, row, col + 0, tf32r(zn0));
                    zh_store(ZH, row, col + 1, tf32r(zn1));
                }
        BAR1();  // z image ready for next step's GEMM1
    }
}

extern "C" void kernel_launch(void* const* d_in, const int* in_sizes, int n_in,
                              void* d_out, int out_size) {
    const float* z0 = (const float*)d_in[0];
    const float* t_range = (const float*)d_in[1];
    const float* W1 = (const float*)d_in[2];
    const float* b1 = (const float*)d_in[3];
    const float* wt = (const float*)d_in[4];
    const float* W2 = (const float*)d_in[5];
    const float* b2 = (const float*)d_in[6];
    float* out = (float*)d_out;

    cudaFuncSetAttribute(ode_main, cudaFuncAttributeMaxDynamicSharedMemorySize, DYN_SMEM);
    ode_prep<<<16, 256>>>(W1, W2);
    ode_main<<<128, 288, DYN_SMEM>>>(z0, t_range, b1, wt, b2, out);
}

// round 6
// speedup vs baseline: 3.3753x; 1.1169x over previous
#include <cuda_runtime.h>
#include <stdint.h>

#define NSTAGE 2
#define CH_ELEMS 8192u   // one 32KB chunk: [4 kt][32 nt][32 lane][2] tf32
#define CH_BYTES 32768u

// dynamic smem layout (bytes)
#define OFF_T 128u                               // t_range 25 f32
#define OFF_BW 256u                              // float2 (b1, wt)[256] -> 2048B
#define OFF_B2 2304u                             // f32 b2[256] -> 1024B
#define OFF_ZH 3584u                             // 128x256 tf32 in A-frag order = 131072B
#define OFF_RING (OFF_ZH + 131072u)              // 134656
#define DYN_SMEM (OFF_RING + NSTAGE * CH_BYTES)  // 200192

// prep output: 16 chunks (W1 slabs 0-7, W2 slabs 8-15) of 32KB in B-frag order
__device__ __align__(128) float g_wblk[16 * CH_ELEMS];

// ---------- helpers ----------
__device__ __forceinline__ uint32_t smem_u32(const void* p) {
    uint32_t a;
    asm("{ .reg .u64 t; cvta.to.shared.u64 t, %1; cvt.u32.u64 %0, t; }" : "=r"(a) : "l"(p));
    return a;
}
__device__ __forceinline__ float tf32r(float x) {
    float y; asm("cvt.rna.tf32.f32 %0, %1;" : "=f"(y) : "f"(x));
    return y;
}
__device__ __forceinline__ float tanh_acc(float x) {
    // tanh(x) = 1 - 2/(1 + e^{2x}); ex2/rcp approx ~2^-22 rel err; correct saturation.
    float u = x * 2.885390081777927f;  // 2*log2(e)
    float e; asm("ex2.approx.f32 %0, %1;" : "=f"(e) : "f"(u));
    float r; asm("rcp.approx.f32 %0, %1;" : "=f"(r) : "f"(e + 1.0f));
    return fmaf(-2.0f, r, 1.0f);
}

#define MBINIT(addr, cnt) \
    asm volatile("mbarrier.init.shared.b64 [%0], %1;" :: "r"(addr), "r"(cnt) : "memory")
#define MB_TX(addr, bytes) \
    asm volatile("mbarrier.arrive.expect_tx.shared.b64 _, [%0], %1;" :: "r"(addr), "r"(bytes) : "memory")
#define MB_ARRIVE(addr) \
    asm volatile("mbarrier.arrive.shared.b64 _, [%0];" :: "r"(addr) : "memory")

#define WAITP(addr, par) do { \
    uint32_t _m = (addr), _p = (par), _d; \
    asm volatile("{\n\t.reg .pred p;\n\t" \
        "mbarrier.try_wait.parity.acquire.cta.shared::cta.b64 p, [%1], %2;\n\t" \
        "selp.b32 %0, 1, 0, p;\n\t}" : "=r"(_d) : "r"(_m), "r"(_p) : "memory"); \
    if (!_d) { \
        asm volatile("{\n\t.reg .pred P1;\n\t" \
            "WL_%=:\n\t" \
            "mbarrier.try_wait.parity.acquire.cta.shared::cta.b64 P1, [%0], %1, 0x989680;\n\t" \
            "@P1 bra.uni WD_%=;\n\tbra.uni WL_%=;\n\tWD_%=:\n\t}" \
            :: "r"(_m), "r"(_p) : "memory"); \
    } \
} while (0)

#define WAITPR(addr, par) do { \
    uint32_t _m = (addr), _p = (par), _d; \
    asm volatile("{\n\t.reg .pred p;\n\t" \
        "mbarrier.try_wait.parity.relaxed.cta.shared::cta.b64 p, [%1], %2, 0x989680;\n\t" \
        "selp.b32 %0, 1, 0, p;\n\t}" : "=r"(_d) : "r"(_m), "r"(_p) : "memory"); \
    if (!_d) { \
        asm volatile("{\n\t.reg .pred P1;\n\t" \
            "WL_%=:\n\t" \
            "mbarrier.try_wait.parity.relaxed.cta.shared::cta.b64 P1, [%0], %1, 0x989680;\n\t" \
            "@P1 bra.uni WD_%=;\n\tbra.uni WL_%=;\n\tWD_%=:\n\t}" \
            :: "r"(_m), "r"(_p) : "memory"); \
    } \
} while (0)

#define BAR1() asm volatile("bar.sync 1, 512;" ::: "memory")

__device__ __forceinline__ void bulk_g2s(uint32_t dst, const void* src, uint32_t bytes, uint32_t mbar) {
    asm volatile(
        "cp.async.bulk.shared::cluster.global.mbarrier::complete_tx::bytes [%0], [%1], %2, [%3];"
        :: "r"(dst), "l"(src), "r"(bytes), "r"(mbar) : "memory");
}

// mma.sync m16n8k8 tf32: d,a,b,c layouts per PTX ISA (g=lane>>2, t=lane&3):
// a0=(g,t) a1=(g+8,t) a2=(g,t+4) a3=(g+8,t+4); b0=(t,g) b1=(t+4,g);
// c0=(g,2t) c1=(g,2t+1) c2=(g+8,2t) c3=(g+8,2t+1)
#define MMA8(d, a, b) \
    asm volatile("mma.sync.aligned.m16n8k8.row.col.f32.tf32.tf32.f32 " \
        "{%0,%1,%2,%3}, {%4,%5,%6,%7}, {%8,%9}, {%0,%1,%2,%3};" \
        : "+f"((d)[0]), "+f"((d)[1]), "+f"((d)[2]), "+f"((d)[3]) \
        : "r"((a).x), "r"((a).y), "r"((a).z), "r"((a).w), "r"((b).x), "r"((b).y))

// A-fragment-order store into ZH: logical (row 0..127, col 0..255)
__device__ __forceinline__ void zh_store(float* ZH, int row, int col, float v) {
    int tile = ((row >> 4) << 5) + (col >> 3);
    int dl = ((row & 7) << 2) + (col & 3);
    int rr = ((row >> 3) & 1) + (((col >> 2) & 1) << 1);
    ZH[tile * 128 + dl * 4 + rr] = v;
}

// ---------- prep: tf32-round + B-fragment-order k-slab images ----------
// chunk b = mat*8 + slab: B[k][n] = W[k][n], k in [slab*32, +32), n in [0,256)
// layout: idx = ((kt*32 + nt)*32 + lane)*2 + r ; k = slab*32+kt*8+(lane&3)+4r ; n = nt*8+(lane>>2)
extern "C" __global__ void __launch_bounds__(256) ode_prep(
    const float* __restrict__ W1, const float* __restrict__ W2) {
    int b = blockIdx.x, mat = b >> 3, slab = b & 7;
    const float* W = mat ? W2 : W1;
    for (int e = threadIdx.x; e < (int)CH_ELEMS; e += 256) {
        int r = e & 1, lane = (e >> 1) & 31, nt = (e >> 6) & 31, kt = e >> 11;
        int k = slab * 32 + kt * 8 + (lane & 3) + 4 * r;
        int n = nt * 8 + (lane >> 2);
        g_wblk[b * CH_ELEMS + e] = tf32r(W[k * 256 + n]);
    }
}

// ---------- GEMM pass: D[32x64 per warp] += A(ZH) @ B(ring), k=256 ----------
__device__ __forceinline__ void gemm_pass(
    float (&d)[2][8][4], const char* smem, uint32_t sb,
    int mi, int ni, int lane, uint32_t& cs, uint32_t& cp) {
    const uint4* A = (const uint4*)(smem + OFF_ZH);
    for (int kc = 0; kc < 8; kc++) {
        WAITP(sb + 16u * cs, cp);
        const uint2* Bk = (const uint2*)(smem + OFF_RING + cs * CH_BYTES);
#pragma unroll
        for (int kk = 0; kk < 4; kk++) {
            const int ktg = kc * 4 + kk;
            uint4 a[2];
#pragma unroll
            for (int i = 0; i < 2; i++) a[i] = A[((mi * 2 + i) * 32 + ktg) * 32 + lane];
            uint2 b[8];
#pragma unroll
            for (int j = 0; j < 8; j++) b[j] = Bk[(kk * 32 + ni * 8 + j) * 32 + lane];
#pragma unroll
            for (int i = 0; i < 2; i++)
#pragma unroll
                for (int j = 0; j < 8; j++) MMA8(d[i][j], a[i], b[j]);
        }
        if (lane == 0) MB_ARRIVE(sb + 48u + 16u * cs);
        cs++; if (cs == NSTAGE) { cs = 0; cp ^= 1; }
    }
}

// ---------- main persistent kernel ----------
// 128 CTAs x 128 rows; warps 0-15 compute (4x4 grid of 32x64 tiles), warp 16 = producer.
extern "C" __global__ void __launch_bounds__(544, 1) ode_main(
    const float* __restrict__ z0, const float* __restrict__ t_range,
    const float* __restrict__ b1, const float* __restrict__ wt,
    const float* __restrict__ b2, float* __restrict__ out) {
    extern __shared__ char smem[];
    const uint32_t sb = smem_u32(smem);
    const int tid = threadIdx.x, w = tid >> 5, lane = tid & 31;
    const int row0 = blockIdx.x * 128;

    float* ZH = (float*)(smem + OFF_ZH);
    float* sT = (float*)(smem + OFF_T);
    float2* sBW = (float2*)(smem + OFF_BW);
    float* sB2 = (float*)(smem + OFF_B2);

    if (tid == 0) {
        for (int s = 0; s < NSTAGE; s++) {
            MBINIT(sb + 16u * s, 1);         // full: producer MB_TX(1 arrive) + bulk bytes
            MBINIT(sb + 48u + 16u * s, 16);  // empty: one arrive per compute warp
        }
    }
    if (tid < 256) {
        sB2[tid] = b2[tid];
        sBW[tid] = make_float2(b1[tid], wt[tid]);
        if (tid < 25) sT[tid] = t_range[tid];
        // init: z master -> out, tf32 image -> ZH (thread owns half a row)
        const int row = tid >> 1, cb = (tid & 1) * 128;
        const float4* zp = (const float4*)(z0 + (size_t)(row0 + row) * 256 + cb);
        float4* op = (float4*)(out + (size_t)(row0 + row) * 256 + cb);
#pragma unroll 4
        for (int q = 0; q < 32; q++) {
            float4 v = zp[q];
            op[q] = v;
            int c = cb + q * 4;
            zh_store(ZH, row, c + 0, tf32r(v.x));
            zh_store(ZH, row, c + 1, tf32r(v.y));
            zh_store(ZH, row, c + 2, tf32r(v.z));
            zh_store(ZH, row, c + 3, tf32r(v.w));
        }
    }
    __syncthreads();

    if (w == 16) {
        // ---- producer: 25 steps x 16 chunks (W1 slabs 0-7 then W2 slabs 8-15) ----
        if (lane == 0) {
            uint32_t es = 0, ep = 1;
            for (int i = 0; i < 400; i++) {
                WAITPR(sb + 48u + 16u * es, ep);
                MB_TX(sb + 16u * es, CH_BYTES);
                bulk_g2s(sb + OFF_RING + es * CH_BYTES, g_wblk + (i & 15) * CH_ELEMS,
                         CH_BYTES, sb + 16u * es);
                es++; if (es == NSTAGE) { es = 0; ep ^= 1; }
            }
        }
        return;
    }

    // ---- compute warps ----
    const int mi = w >> 2, ni = w & 3;  // warp tile: rows [mi*32,+32), cols [ni*64,+64)
    const int gid = lane >> 2, tig = lane & 3;
    const float dt = sT[1] - sT[0];
    uint32_t cs = 0, cp = 0;
    float d[2][8][4];

    for (int s = 0; s < 25; s++) {
        const float t = sT[s];
        // ---- GEMM1: D = z @ W1 ----
#pragma unroll
        for (int i = 0; i < 2; i++)
#pragma unroll
            for (int j = 0; j < 8; j++)
#pragma unroll
                for (int r = 0; r < 4; r++) d[i][j][r] = 0.0f;
        gemm_pass(d, smem, sb, mi, ni, lane, cs, cp);
        BAR1();  // all warps done reading ZH (z)
        // ---- h = tanh(D + b1 + t*wt) -> ZH (tf32, A-frag order; col is GEMM2's k) ----
#pragma unroll
        for (int i = 0; i < 2; i++)
#pragma unroll
            for (int j = 0; j < 8; j++)
#pragma unroll
                for (int r = 0; r < 4; r++) {
                    int row = mi * 32 + i * 16 + gid + ((r & 2) ? 8 : 0);
                    int col = ni * 64 + j * 8 + 2 * tig + (r & 1);
                    float2 bw = sBW[col];
                    float x = d[i][j][r] + bw.x + t * bw.y;
                    zh_store(ZH, row, col, tf32r(tanh_acc(x)));
                }
        BAR1();  // h fully written
        // ---- GEMM2: D = h @ W2 ----
#pragma unroll
        for (int i = 0; i < 2; i++)
#pragma unroll
            for (int j = 0; j < 8; j++)
#pragma unroll
                for (int r = 0; r < 4; r++) d[i][j][r] = 0.0f;
        gemm_pass(d, smem, sb, mi, ni, lane, cs, cp);
        BAR1();  // all warps done reading ZH (h)
        // ---- z update: z += dt*(D + b2); fp32 master in out, tf32 image -> ZH ----
#pragma unroll
        for (int i = 0; i < 2; i++)
#pragma unroll
            for (int j = 0; j < 8; j++)
#pragma unroll
                for (int rp = 0; rp < 2; rp++) {
                    int row = mi * 32 + i * 16 + gid + rp * 8;
                    int col = ni * 64 + j * 8 + 2 * tig;
                    size_t g = (size_t)(row0 + row) * 256 + col;
                    float2 zo = *(const float2*)(out + g);
                    float zn0 = fmaf(dt, d[i][j][2 * rp + 0] + sB2[col + 0], zo.x);
                    float zn1 = fmaf(dt, d[i][j][2 * rp + 1] + sB2[col + 1], zo.y);
                    *(float2*)(out + g) = make_float2(zn0, zn1);
                    zh_store(ZH, row, col + 0, tf32r(zn0));
                    zh_store(ZH, row, col + 1, tf32r(zn1));
                }
        BAR1();  // z image ready for next step's GEMM1
    }
}

extern "C" void kernel_launch(void* const* d_in, const int* in_sizes, int n_in,
                              void* d_out, int out_size) {
    const float* z0 = (const float*)d_in[0];
    const float* t_range = (const float*)d_in[1];
    const float* W1 = (const float*)d_in[2];
    const float* b1 = (const float*)d_in[3];
    const float* wt = (const float*)d_in[4];
    const float* W2 = (const float*)d_in[5];
    const float* b2 = (const float*)d_in[6];
    float* out = (float*)d_out;

    cudaFuncSetAttribute(ode_main, cudaFuncAttributeMaxDynamicSharedMemorySize, DYN_SMEM);
    ode_prep<<<16, 256>>>(W1, W2);
    ode_main<<<128, 544, DYN_SMEM>>>(z0, t_range, b1, wt, b2, out);
}